// round 8
// baseline (speedup 1.0000x reference)
#include <cuda_runtime.h>
#include <cuda_bf16.h>
#include <cstdint>

#define NN 50000
#define EE 600000
#define GG 512
#define HH 128
#define NB 196          // scan blocks = ceil(NN/256)
#define AST 136         // padded smem stride in bf16 elements (conflict-free ldmatrix)

// ---------------- scratch (device globals; no allocation allowed) -------------
__device__ float    g_dinv[NN];
__device__ int      g_cnt[NN];
__device__ int      g_off[NN + 1];
__device__ int      g_pos[NN];
__device__ int      g_bsum[256];
__device__ int      g_gstart[GG + 1];
__device__ int      g_csr[EE];
__device__ float    g_h   [NN * HH];
__device__ float    g_agg [NN * HH];
__device__ float    g_gate[NN];
__device__ float    g_pooled[GG * HH];

// ---------------- helpers ----------------
__device__ __forceinline__ uint32_t smem_u32(const void* p) {
    return (uint32_t)__cvta_generic_to_shared(p);
}
__device__ __forceinline__ void ldm_x4(uint32_t addr, uint32_t& r0, uint32_t& r1,
                                       uint32_t& r2, uint32_t& r3) {
    asm volatile("ldmatrix.sync.aligned.m8n8.x4.shared.b16 {%0,%1,%2,%3}, [%4];"
                 : "=r"(r0), "=r"(r1), "=r"(r2), "=r"(r3) : "r"(addr));
}
__device__ __forceinline__ void mma_bf16(float* c, const uint32_t* a,
                                         const uint32_t* b) {
    asm volatile(
        "mma.sync.aligned.m16n8k16.row.col.f32.bf16.bf16.f32 "
        "{%0,%1,%2,%3}, {%4,%5,%6,%7}, {%8,%9}, {%0,%1,%2,%3};"
        : "+f"(c[0]), "+f"(c[1]), "+f"(c[2]), "+f"(c[3])
        : "r"(a[0]), "r"(a[1]), "r"(a[2]), "r"(a[3]), "r"(b[0]), "r"(b[1]));
}
__device__ __forceinline__ uint32_t bf2u(__nv_bfloat16 a, __nv_bfloat16 b) {
    __nv_bfloat162 p = __halves2bfloat162(a, b);
    return *(uint32_t*)&p;
}

// ---------------- tensor GEMM: acc[n,128] = X[n,128] @ W[128,128] -------------
// bf16 split: D = Ah*Bh + Ah*Bl + Al*Bh accumulated in fp32 fragments.
// 256 threads = 8 warps (4 M-warps x 2 N-warps), tile 128x128, K=128 whole.
// Modes:
//   AGG != null : Y = acc ; AGG = agg_bias + acc * dinv[row]^2   (layer mode)
//   GW2 != null : gate mode — g_gate[row] = relu(acc+bias_out).GW2 + gb2
__global__ void __launch_bounds__(256, 1)
k_gemmT(const float* __restrict__ X, const float* __restrict__ W,
        const float* __restrict__ bias_out, const float* __restrict__ agg_bias,
        float* __restrict__ Y, float* __restrict__ AGG,
        const float* __restrict__ GW2, const float* __restrict__ gb2, int n) {
    extern __shared__ char smem[];
    __nv_bfloat16* Ah = (__nv_bfloat16*)smem;           // [128][AST]
    __nv_bfloat16* Al = Ah + 128 * AST;
    __nv_bfloat16* Bh = Al + 128 * AST;                 // Wt hi: [n][k]
    __nv_bfloat16* Bl = Bh + 128 * AST;
    float* sg = (float*)(Bl + 128 * AST);               // [2][128] gate partials

    const int tid = threadIdx.x;
    const int wid = tid >> 5;
    const int l = tid & 31;
    const int wm = wid >> 1;         // 0..3 -> M rows 32*wm
    const int wn = wid & 1;          // 0..1 -> N cols 64*wn
    const int row0 = blockIdx.x * 128;

    // ---- load X tile -> Ah/Al (row-major [r][k], padded) ----
#pragma unroll
    for (int it = 0; it < 16; it++) {
        int idx = tid + it * 256;        // 0..4095
        int r = idx >> 5;                // 0..127
        int c4 = idx & 31;
        int gr = row0 + r;
        float4 v = make_float4(0.f, 0.f, 0.f, 0.f);
        if (gr < n) v = ((const float4*)(X + (size_t)gr * 128))[c4];
        __nv_bfloat16 h0 = __float2bfloat16_rn(v.x);
        __nv_bfloat16 h1 = __float2bfloat16_rn(v.y);
        __nv_bfloat16 h2 = __float2bfloat16_rn(v.z);
        __nv_bfloat16 h3 = __float2bfloat16_rn(v.w);
        __nv_bfloat16 l0 = __float2bfloat16_rn(v.x - __bfloat162float(h0));
        __nv_bfloat16 l1 = __float2bfloat16_rn(v.y - __bfloat162float(h1));
        __nv_bfloat16 l2 = __float2bfloat16_rn(v.z - __bfloat162float(h2));
        __nv_bfloat16 l3 = __float2bfloat16_rn(v.w - __bfloat162float(h3));
        int off = r * AST + c4 * 4;
        *(uint2*)&Ah[off] = make_uint2(bf2u(h0, h1), bf2u(h2, h3));
        *(uint2*)&Al[off] = make_uint2(bf2u(l0, l1), bf2u(l2, l3));
    }
    // ---- load W -> Bh/Bl transposed ([n][k], padded) ----
#pragma unroll
    for (int it = 0; it < 16; it++) {
        int idx = tid + it * 256;
        int k = idx >> 5;
        int c4 = idx & 31;
        float4 v = ((const float4*)(W + (size_t)k * 128))[c4];
        float vv[4] = {v.x, v.y, v.z, v.w};
#pragma unroll
        for (int j = 0; j < 4; j++) {
            int nc = c4 * 4 + j;
            __nv_bfloat16 h = __float2bfloat16_rn(vv[j]);
            __nv_bfloat16 lo = __float2bfloat16_rn(vv[j] - __bfloat162float(h));
            Bh[nc * AST + k] = h;
            Bl[nc * AST + k] = lo;
        }
    }
    __syncthreads();

    // ---- fragments & accumulators ----
    float c[2][8][4];
#pragma unroll
    for (int mt = 0; mt < 2; mt++)
#pragma unroll
        for (int nt = 0; nt < 8; nt++)
#pragma unroll
            for (int q = 0; q < 4; q++) c[mt][nt][q] = 0.0f;

    const int aRow = ((l & 8) ? 8 : 0) + (l & 7);
    const int aK   = (l & 16) ? 8 : 0;
    const int bN   = ((l & 16) ? 8 : 0) + (l & 7);
    const int bK   = (l & 8) ? 8 : 0;

    const uint32_t ah = smem_u32(Ah), al = smem_u32(Al);
    const uint32_t bh = smem_u32(Bh), bl = smem_u32(Bl);

#pragma unroll
    for (int pass = 0; pass < 3; pass++) {
        const uint32_t ab = (pass == 2) ? al : ah;
        const uint32_t bb = (pass == 1) ? bl : bh;
#pragma unroll
        for (int ks = 0; ks < 8; ks++) {
            uint32_t bfr[8][2];
#pragma unroll
            for (int np = 0; np < 4; np++) {
                uint32_t addr = bb +
                    ((wn * 64 + np * 16 + bN) * AST + ks * 16 + bK) * 2;
                ldm_x4(addr, bfr[2 * np][0], bfr[2 * np][1],
                       bfr[2 * np + 1][0], bfr[2 * np + 1][1]);
            }
            uint32_t afr[2][4];
#pragma unroll
            for (int mt = 0; mt < 2; mt++) {
                uint32_t addr = ab +
                    ((wm * 32 + mt * 16 + aRow) * AST + ks * 16 + aK) * 2;
                ldm_x4(addr, afr[mt][0], afr[mt][1], afr[mt][2], afr[mt][3]);
            }
#pragma unroll
            for (int mt = 0; mt < 2; mt++)
#pragma unroll
                for (int nt = 0; nt < 8; nt++)
                    mma_bf16(c[mt][nt], afr[mt], bfr[nt]);
        }
    }

    const int g = l >> 2;
    const int q2 = 2 * (l & 3);

    if (GW2) {
        // ---- gate epilogue: dot(relu(acc+gb1), gw2) per row ----
        float ds[2][2] = {{0.f, 0.f}, {0.f, 0.f}};
#pragma unroll
        for (int nt = 0; nt < 8; nt++) {
            int col = wn * 64 + nt * 8 + q2;
            float b0 = bias_out[col], b1 = bias_out[col + 1];
            float w0 = GW2[col], w1 = GW2[col + 1];
#pragma unroll
            for (int mt = 0; mt < 2; mt++) {
                ds[mt][0] += fmaxf(c[mt][nt][0] + b0, 0.f) * w0 +
                             fmaxf(c[mt][nt][1] + b1, 0.f) * w1;
                ds[mt][1] += fmaxf(c[mt][nt][2] + b0, 0.f) * w0 +
                             fmaxf(c[mt][nt][3] + b1, 0.f) * w1;
            }
        }
#pragma unroll
        for (int mt = 0; mt < 2; mt++)
#pragma unroll
            for (int hf = 0; hf < 2; hf++) {
                float d = ds[mt][hf];
                d += __shfl_xor_sync(0xFFFFFFFFu, d, 1);
                d += __shfl_xor_sync(0xFFFFFFFFu, d, 2);
                if ((l & 3) == 0)
                    sg[wn * 128 + wm * 32 + mt * 16 + hf * 8 + g] = d;
            }
        __syncthreads();
        if (tid < 128) {
            int row = row0 + tid;
            if (row < n) g_gate[row] = sg[tid] + sg[128 + tid] + gb2[0];
        }
        return;
    }

    // ---- layer epilogue: Y = acc ; AGG = agg_bias + acc*dinv^2 ----
#pragma unroll
    for (int mt = 0; mt < 2; mt++) {
#pragma unroll
        for (int hf = 0; hf < 2; hf++) {
            int row = row0 + wm * 32 + mt * 16 + hf * 8 + g;
            if (row >= n) continue;
            float di = g_dinv[row];
            float w2 = di * di;
#pragma unroll
            for (int nt = 0; nt < 8; nt++) {
                int col = wn * 64 + nt * 8 + q2;
                float v0 = c[mt][nt][hf * 2 + 0];
                float v1 = c[mt][nt][hf * 2 + 1];
                *(float2*)(Y + (size_t)row * 128 + col) = make_float2(v0, v1);
                float a0 = agg_bias[col] + v0 * w2;
                float a1 = agg_bias[col + 1] + v1 * w2;
                *(float2*)(AGG + (size_t)row * 128 + col) = make_float2(a0, a1);
            }
        }
    }
}

// ---------------- preprocessing ----------------------------------------------
__global__ void k_init() {
    int i = blockIdx.x * blockDim.x + threadIdx.x;
    if (i < NN) g_cnt[i] = 0;
}

__global__ void k_deg(const int* __restrict__ ei) {
    int i = blockIdx.x * blockDim.x + threadIdx.x;
    if (i < EE) atomicAdd(&g_cnt[ei[EE + i]], 1);
}

__global__ void k_scan1() {
    __shared__ int sh[256];
    int i = blockIdx.x * 256 + threadIdx.x;
    int v = (i < NN) ? g_cnt[i] : 0;
    if (i < NN) g_dinv[i] = rsqrtf((float)(v + 1));   // +1 self loop
    sh[threadIdx.x] = v;
    __syncthreads();
    for (int off = 1; off < 256; off <<= 1) {
        int t = (threadIdx.x >= off) ? sh[threadIdx.x - off] : 0;
        __syncthreads();
        sh[threadIdx.x] += t;
        __syncthreads();
    }
    if (i < NN) g_off[i] = sh[threadIdx.x] - v;
    if (threadIdx.x == 255) g_bsum[blockIdx.x] = sh[255];
}

__global__ void k_scan23() {
    __shared__ int sh[256];
    int t = threadIdx.x;
    int v = (t < NB) ? g_bsum[t] : 0;
    sh[t] = v;
    __syncthreads();
    for (int off = 1; off < 256; off <<= 1) {
        int u = (t >= off) ? sh[t - off] : 0;
        __syncthreads();
        sh[t] += u;
        __syncthreads();
    }
    int boff = sh[blockIdx.x] - g_bsum[blockIdx.x];
    __syncthreads();
    int i = blockIdx.x * 256 + t;
    if (i < NN) {
        int o = g_off[i] + boff;
        g_off[i] = o;
        g_pos[i] = o;
    }
    if (i == 0) g_off[NN] = EE;
}

__global__ void k_fill(const int* __restrict__ ei) {
    int e = blockIdx.x * blockDim.x + threadIdx.x;
    if (e >= EE) return;
    int d = ei[EE + e];
    int p = atomicAdd(&g_pos[d], 1);
    g_csr[p] = ei[e];
}

__global__ void k_bound(const int* __restrict__ batch) {
    int i = blockIdx.x * blockDim.x + threadIdx.x;
    if (i >= NN) return;
    int b = batch[i];
    if (i == 0) {
        for (int g = 0; g <= b; g++) g_gstart[g] = 0;
    } else {
        int p = batch[i - 1];
        for (int g = p + 1; g <= b; g++) g_gstart[g] = i;
    }
    if (i == NN - 1) {
        for (int g = b + 1; g <= GG; g++) g_gstart[g] = NN;
    }
}

// ---------------- CSR gather + LayerNorm + ReLU (warp per dst node) -----------
__global__ void k_aggcsr(const float* __restrict__ h, float* __restrict__ agg,
                         const float* __restrict__ gamma,
                         const float* __restrict__ beta) {
    int node = blockIdx.x * 8 + (threadIdx.x >> 5);
    int lane = threadIdx.x & 31;
    if (node >= NN) return;

    float4 a0 = ((const float4*)agg)[(size_t)node * 32 + lane];
    float4 a1 = make_float4(0.f, 0.f, 0.f, 0.f);
    float4 a2 = make_float4(0.f, 0.f, 0.f, 0.f);
    float4 a3 = make_float4(0.f, 0.f, 0.f, 0.f);
    int e = g_off[node];
    const int end = g_off[node + 1];
    const float dd = g_dinv[node];

    for (; e + 3 < end; e += 4) {
        int s0 = g_csr[e],     s1 = g_csr[e + 1];
        int s2 = g_csr[e + 2], s3 = g_csr[e + 3];
        float w0 = g_dinv[s0] * dd, w1 = g_dinv[s1] * dd;
        float w2 = g_dinv[s2] * dd, w3 = g_dinv[s3] * dd;
        float4 h0 = ((const float4*)h)[(size_t)s0 * 32 + lane];
        float4 h1 = ((const float4*)h)[(size_t)s1 * 32 + lane];
        float4 h2 = ((const float4*)h)[(size_t)s2 * 32 + lane];
        float4 h3 = ((const float4*)h)[(size_t)s3 * 32 + lane];
        a0.x += h0.x * w0; a0.y += h0.y * w0; a0.z += h0.z * w0; a0.w += h0.w * w0;
        a1.x += h1.x * w1; a1.y += h1.y * w1; a1.z += h1.z * w1; a1.w += h1.w * w1;
        a2.x += h2.x * w2; a2.y += h2.y * w2; a2.z += h2.z * w2; a2.w += h2.w * w2;
        a3.x += h3.x * w3; a3.y += h3.y * w3; a3.z += h3.z * w3; a3.w += h3.w * w3;
    }
    for (; e < end; e++) {
        int s0 = g_csr[e];
        float w0 = g_dinv[s0] * dd;
        float4 h0 = ((const float4*)h)[(size_t)s0 * 32 + lane];
        a0.x += h0.x * w0; a0.y += h0.y * w0; a0.z += h0.z * w0; a0.w += h0.w * w0;
    }
    a0.x += a1.x + a2.x + a3.x;
    a0.y += a1.y + a2.y + a3.y;
    a0.z += a1.z + a2.z + a3.z;
    a0.w += a1.w + a2.w + a3.w;

    float s = a0.x + a0.y + a0.z + a0.w;
#pragma unroll
    for (int off = 16; off; off >>= 1) s += __shfl_xor_sync(0xFFFFFFFFu, s, off);
    float m = s * (1.0f / 128.0f);
    float dx = a0.x - m, dy = a0.y - m, dz = a0.z - m, dw = a0.w - m;
    float q = dx * dx + dy * dy + dz * dz + dw * dw;
#pragma unroll
    for (int off = 16; off; off >>= 1) q += __shfl_xor_sync(0xFFFFFFFFu, q, off);
    float rinv = rsqrtf(q * (1.0f / 128.0f) + 1e-5f);
    float4 gv = ((const float4*)gamma)[lane];
    float4 bv = ((const float4*)beta)[lane];
    float4 o;
    o.x = fmaxf(dx * rinv * gv.x + bv.x, 0.f);
    o.y = fmaxf(dy * rinv * gv.y + bv.y, 0.f);
    o.z = fmaxf(dz * rinv * gv.z + bv.z, 0.f);
    o.w = fmaxf(dw * rinv * gv.w + bv.w, 0.f);
    ((float4*)agg)[(size_t)node * 32 + lane] = o;
}

// ---------------- segment-contiguous attention pooling (block per graph) ------
__global__ void k_poolseg(const float* __restrict__ h) {
    __shared__ float sa[1024];
    __shared__ float red[128];
    const int g = blockIdx.x;
    const int t = threadIdx.x;
    const int s = g_gstart[g];
    const int e = g_gstart[g + 1];

    if (s >= e) {
        g_pooled[(size_t)g * 128 + t] = 0.0f;
        return;
    }

    float m = -3.402823466e+38f;
    for (int i = s + t; i < e; i += 128) m = fmaxf(m, g_gate[i]);
    red[t] = m;
    __syncthreads();
    for (int off = 64; off; off >>= 1) {
        if (t < off) red[t] = fmaxf(red[t], red[t + off]);
        __syncthreads();
    }
    m = red[0];
    __syncthreads();

    float acc = 0.0f;
    float dloc = 0.0f;
    for (int c = s; c < e; c += 1024) {
        int len = min(1024, e - c);
        for (int j = t; j < len; j += 128) {
            float a = expf(g_gate[c + j] - m);
            sa[j] = a;
            dloc += a;
        }
        __syncthreads();
#pragma unroll 4
        for (int j = 0; j < len; j++)
            acc += sa[j] * h[(size_t)(c + j) * 128 + t];
        __syncthreads();
    }
    red[t] = dloc;
    __syncthreads();
    for (int off = 64; off; off >>= 1) {
        if (t < off) red[t] += red[t + off];
        __syncthreads();
    }
    g_pooled[(size_t)g * 128 + t] = acc / red[0];
}

// ---------------- classifier --------------------------------------------------
__global__ void k_cls(const float* __restrict__ cw1, const float* __restrict__ cb1,
                      const float* __restrict__ cw2, const float* __restrict__ cb2,
                      float* __restrict__ out) {
    __shared__ float p[128];
    __shared__ float s0[128];
    __shared__ float s1[128];
    int g = blockIdx.x;
    int t = threadIdx.x;
    p[t] = g_pooled[(size_t)g * 128 + t];
    __syncthreads();
    float acc = cb1[t];
#pragma unroll 8
    for (int k = 0; k < 128; k++) acc += p[k] * cw1[k * 128 + t];
    acc = fmaxf(acc, 0.0f);
    s0[t] = acc * cw2[t * 2 + 0];
    s1[t] = acc * cw2[t * 2 + 1];
    __syncthreads();
    for (int off = 64; off; off >>= 1) {
        if (t < off) { s0[t] += s0[t + off]; s1[t] += s1[t + off]; }
        __syncthreads();
    }
    if (t == 0) {
        out[g * 2 + 0] = s0[0] + cb2[0];
        out[g * 2 + 1] = s1[0] + cb2[1];
    }
}

// ---------------- launch ------------------------------------------------------
#define TSMEM (4 * 128 * AST * 2 + 2 * 128 * 4)

extern "C" void kernel_launch(void* const* d_in, const int* in_sizes, int n_in,
                              void* d_out, int out_size) {
    const float* x      = (const float*)d_in[0];
    const int*   ei     = (const int*)  d_in[1];
    const int*   batch  = (const int*)  d_in[2];
    const float* W1     = (const float*)d_in[3];
    const float* b1     = (const float*)d_in[4];
    const float* ln1g   = (const float*)d_in[5];
    const float* ln1b   = (const float*)d_in[6];
    const float* W2     = (const float*)d_in[7];
    const float* b2     = (const float*)d_in[8];
    const float* ln2g   = (const float*)d_in[9];
    const float* ln2b   = (const float*)d_in[10];
    const float* gw1    = (const float*)d_in[11];
    const float* gb1    = (const float*)d_in[12];
    const float* gw2    = (const float*)d_in[13];
    const float* gb2    = (const float*)d_in[14];
    const float* cw1    = (const float*)d_in[15];
    const float* cb1    = (const float*)d_in[16];
    const float* cw2    = (const float*)d_in[17];
    const float* cb2    = (const float*)d_in[18];
    float* out = (float*)d_out;

    float* hbuf;   cudaGetSymbolAddress((void**)&hbuf, g_h);
    float* abuf;   cudaGetSymbolAddress((void**)&abuf, g_agg);

    cudaFuncSetAttribute(k_gemmT, cudaFuncAttributeMaxDynamicSharedMemorySize,
                         TSMEM);

    const int T = 256;
    // ---- preprocessing: degree, dinv, CSR, graph bounds ----
    k_init<<<(NN + T - 1) / T, T>>>();
    k_deg<<<(EE + T - 1) / T, T>>>(ei);
    k_scan1<<<NB, 256>>>();
    k_scan23<<<NB, 256>>>();
    k_fill<<<(EE + T - 1) / T, T>>>(ei);
    k_bound<<<(NN + T - 1) / T, T>>>(batch);

    int gemm_blocks = (NN + 127) / 128;        // 391
    int agg_blocks  = (NN + 7) / 8;

    // ---- layer 1 ----
    k_gemmT<<<gemm_blocks, T, TSMEM>>>(x, W1, nullptr, b1, hbuf, abuf,
                                       nullptr, nullptr, NN);
    k_aggcsr<<<agg_blocks, T>>>(hbuf, abuf, ln1g, ln1b);

    // ---- layer 2 ----
    k_gemmT<<<gemm_blocks, T, TSMEM>>>(abuf, W2, nullptr, b2, hbuf, abuf,
                                       nullptr, nullptr, NN);
    k_aggcsr<<<agg_blocks, T>>>(hbuf, abuf, ln2g, ln2b);

    // ---- attention pooling (gate fused into GEMM; segment pooling) ----
    k_gemmT<<<gemm_blocks, T, TSMEM>>>(abuf, gw1, gb1, nullptr, nullptr, nullptr,
                                       gw2, gb2, NN);
    k_poolseg<<<GG, 128>>>(abuf);

    // ---- classifier ----
    k_cls<<<GG, 128>>>(cw1, cb1, cw2, cb2, out);
}